// round 5
// baseline (speedup 1.0000x reference)
#include <cuda_runtime.h>
#include <cstdint>

// Problem constants (fixed by the reference)
#define NU 200000
#define NI 400000
#define NN 600000          // NU + NI
#define DD 32
#define NH 128
#define NE 10000000

#define GB_USER 384
#define GB_ITEM 768

// Scratch: device globals (no allocation allowed)
__device__ __align__(256) float g_bufA[(size_t)NN * DD];
__device__ __align__(256) float g_bufB[(size_t)NN * DD];
__device__ __align__(256) float g_G[2][DD * DD];
__device__ __align__(256) float g_M[2][DD * DD];
__device__ int g_is64;

// ---------------- helpers ----------------
__device__ __forceinline__ float4 f4_fma(float a, float4 b, float4 c) {
    c.x = fmaf(a, b.x, c.x);
    c.y = fmaf(a, b.y, c.y);
    c.z = fmaf(a, b.z, c.z);
    c.w = fmaf(a, b.w, c.w);
    return c;
}

__device__ __forceinline__ void red_add_v4(float* p, float4 v) {
    asm volatile("red.global.add.v4.f32 [%0], {%1,%2,%3,%4};"
                 :: "l"(p), "f"(v.x), "f"(v.y), "f"(v.z), "f"(v.w)
                 : "memory");
}

__device__ __forceinline__ float lrelu(float x) {
    return fmaxf(x, 0.5f * x);   // negative_slope = 0.5
}

// ---------------- kernels ----------------

// Detect whether adj_idx is int64 (x64 refs) or int32: int64 values < 2^31
// have all-zero high words at odd int32 slots.
__global__ void k_detect(const int* __restrict__ adj) {
    if (threadIdx.x == 0 && blockIdx.x == 0) {
        int odd_or = 0;
        #pragma unroll 8
        for (int i = 1; i < 2048; i += 2) odd_or |= adj[i];
        g_is64 = (odd_or == 0) ? 1 : 0;
    }
}

// prev(A) = concat(user_emb, item_emb); out = same (accumulator seed)
__global__ void __launch_bounds__(256)
k_init(const float* __restrict__ ue, const float* __restrict__ ie,
       float* __restrict__ out) {
    size_t i = (size_t)blockIdx.x * blockDim.x + threadIdx.x;   // float4 index
    const size_t nu4 = (size_t)NU * DD / 4;
    const size_t tot = (size_t)NN * DD / 4;
    if (i >= tot) return;
    float4 v = (i < nu4) ? ((const float4*)ue)[i] : ((const float4*)ie)[i - nu4];
    ((float4*)g_bufA)[i] = v;
    ((float4*)out)[i] = v;
}

__global__ void __launch_bounds__(512)
k_zeroG() {
    int t = threadIdx.x;
    float* g = &g_G[0][0];
    for (int i = t; i < 2 * DD * DD; i += blockDim.x) g[i] = 0.0f;
}

// G[part] = E0_part^T @ prev_part   (32x32 each)
__global__ void __launch_bounds__(256, 2)
k_G(const float* __restrict__ ue, const float* __restrict__ ie, int dir) {
    const float* prev = dir ? g_bufB : g_bufA;
    int b = blockIdx.x;
    const float* e0; const float* pv; float* Gout; int r0, r1;
    if (b < GB_USER) {
        e0 = ue; pv = prev; Gout = g_G[0];
        const int per = (NU + GB_USER - 1) / GB_USER;
        r0 = b * per; r1 = min(r0 + per, NU);
    } else {
        int bb = b - GB_USER;
        e0 = ie; pv = prev + (size_t)NU * DD; Gout = g_G[1];
        const int per = (NI + GB_ITEM - 1) / GB_ITEM;
        r0 = bb * per; r1 = min(r0 + per, NI);
    }
    int t = threadIdx.x;
    int q  = t >> 6;          // row subgroup 0..3
    int g  = t & 63;          // cell-thread 0..63
    int a4 = g >> 3;          // 0..7 -> rows a4*4..+3 of G
    int b4 = g & 7;           // 0..7 -> cols b4*4..+3 of G

    float4 acc0 = {0,0,0,0}, acc1 = {0,0,0,0}, acc2 = {0,0,0,0}, acc3 = {0,0,0,0};

    #pragma unroll 2
    for (int r = r0 + q; r < r1; r += 4) {
        float4 e4 = *(const float4*)(e0 + (size_t)r * DD + a4 * 4);
        float4 p4 = *(const float4*)(pv + (size_t)r * DD + b4 * 4);
        acc0 = f4_fma(e4.x, p4, acc0);
        acc1 = f4_fma(e4.y, p4, acc1);
        acc2 = f4_fma(e4.z, p4, acc2);
        acc3 = f4_fma(e4.w, p4, acc3);
    }

    __shared__ float red[4 * 1024];
    float* my = red + q * 1024 + g * 16;
    ((float4*)my)[0] = acc0;
    ((float4*)my)[1] = acc1;
    ((float4*)my)[2] = acc2;
    ((float4*)my)[3] = acc3;
    __syncthreads();

    for (int idx = t; idx < 1024; idx += 256) {
        int gg = idx >> 4, i = idx & 15;
        float s = red[0 * 1024 + gg * 16 + i] + red[1 * 1024 + gg * 16 + i]
                + red[2 * 1024 + gg * 16 + i] + red[3 * 1024 + gg * 16 + i];
        int a  = (gg >> 3) * 4 + (i >> 2);
        int bc = (gg & 7) * 4 + (i & 3);
        atomicAdd(&Gout[a * DD + bc], s);
    }
}

// M[part] = W (W^T G[part]);  W is [32,128] row-major. grid = 2 blocks, 256 thr.
__global__ void __launch_bounds__(256, 1)
k_M(const float* __restrict__ uW, const float* __restrict__ iW) {
    int part = blockIdx.x;
    const float* W = part ? iW : uW;
    __shared__ float Wsh[32 * NH];
    __shared__ float Tsh[NH * 32];
    __shared__ float Gsh[32 * 32];
    int t = threadIdx.x;
    for (int i = t; i < 32 * NH; i += 256) Wsh[i] = W[i];
    for (int i = t; i < 1024; i += 256) Gsh[i] = g_G[part][i];
    __syncthreads();
    // T = W^T G : [128, 32]
    for (int idx = t; idx < NH * 32; idx += 256) {
        int h = idx >> 5, bcol = idx & 31;
        float s = 0.0f;
        #pragma unroll 8
        for (int a = 0; a < 32; a++) s = fmaf(Wsh[a * NH + h], Gsh[a * 32 + bcol], s);
        Tsh[h * 32 + bcol] = s;
    }
    __syncthreads();
    // M = W T : [32, 32]
    for (int idx = t; idx < 1024; idx += 256) {
        int a = idx >> 5, bcol = idx & 31;
        float s = 0.0f;
        #pragma unroll 8
        for (int h = 0; h < NH; h++) s = fmaf(Wsh[a * NH + h], Tsh[h * 32 + bcol], s);
        g_M[part][idx] = s;
    }
}

// dst = leaky_relu(E0 @ M[part]); warp handles 4 rows, 8 threads per row.
__global__ void __launch_bounds__(256)
k_hyp(const float* __restrict__ ue, const float* __restrict__ ie, int dir) {
    float* dst = dir ? g_bufA : g_bufB;
    __shared__ float4 Msh[512];                // [part*256 + a*8 + c4]
    int t = threadIdx.x;
    for (int i = t; i < 512; i += 256) Msh[i] = ((const float4*)g_M)[i];
    __syncthreads();

    int warp = t >> 5, lane = t & 31;
    int rr = lane >> 3, c4 = lane & 7;
    int row = (blockIdx.x * 8 + warp) * 4 + rr;
    if (row >= NN) return;

    const float* e0row;
    int part;
    if (row < NU) { e0row = ue + (size_t)row * DD; part = 0; }
    else          { e0row = ie + (size_t)(row - NU) * DD; part = 1; }

    const float4* Mp = Msh + part * 256 + c4;
    float4 acc = {0,0,0,0};
    #pragma unroll
    for (int i = 0; i < 8; i++) {
        float4 ev = ((const float4*)e0row)[i];
        acc = f4_fma(ev.x, Mp[(i * 4 + 0) * 8], acc);
        acc = f4_fma(ev.y, Mp[(i * 4 + 1) * 8], acc);
        acc = f4_fma(ev.z, Mp[(i * 4 + 2) * 8], acc);
        acc = f4_fma(ev.w, Mp[(i * 4 + 3) * 8], acc);
    }
    float4 o;
    o.x = lrelu(acc.x); o.y = lrelu(acc.y); o.z = lrelu(acc.z); o.w = lrelu(acc.w);
    ((float4*)(dst + (size_t)row * DD))[c4] = o;
}

// dst[r] += v * src[c] over all edges; 8 threads per edge, vectorized red.
__global__ void __launch_bounds__(256)
k_spmm(const int* __restrict__ adj, const float* __restrict__ vals, int dir) {
    const float* src = dir ? g_bufB : g_bufA;
    float*       dst = dir ? g_bufA : g_bufB;
    size_t tid = (size_t)blockIdx.x * blockDim.x + threadIdx.x;
    size_t e = tid >> 3;
    int c8 = (int)(tid & 7);
    if (e >= (size_t)NE) return;
    int r, c;
    if (g_is64) {
        const long long* a64 = (const long long*)adj;
        r = (int)__ldcs(a64 + e);
        c = (int)__ldcs(a64 + (size_t)NE + e);
    } else {
        r = __ldcs(adj + e);
        c = __ldcs(adj + (size_t)NE + e);
    }
    float v = __ldcs(vals + e);
    float4 p = *(const float4*)(src + (size_t)c * DD + c8 * 4);
    float4 m = make_float4(v * p.x, v * p.y, v * p.z, v * p.w);
    red_add_v4(dst + (size_t)r * DD + c8 * 4, m);
}

// out += layer buffer
__global__ void __launch_bounds__(256)
k_accum(float* __restrict__ out, int dir) {
    const float* src = dir ? g_bufA : g_bufB;
    size_t i = (size_t)blockIdx.x * blockDim.x + threadIdx.x;
    if (i >= (size_t)NN * DD / 4) return;
    float4 s = ((const float4*)src)[i];
    float4 o = ((float4*)out)[i];
    o.x += s.x; o.y += s.y; o.z += s.z; o.w += s.w;
    ((float4*)out)[i] = o;
}

// ---------------- launch ----------------
extern "C" void kernel_launch(void* const* d_in, const int* in_sizes, int n_in,
                              void* d_out, int out_size) {
    // Identify inputs by element count (robust to harness ordering)
    const int* adj = nullptr; const float* vals = nullptr;
    const float* ue = nullptr; const float* ie = nullptr;
    const float* h1 = nullptr; const float* h2 = nullptr;
    int i_ue = -1, i_ie = -1;
    for (int i = 0; i < n_in; i++) {
        long long s = in_sizes[i];
        if (s == 2LL * NE)              adj = (const int*)d_in[i];
        else if (s == (long long)NE)    vals = (const float*)d_in[i];
        else if (s == (long long)NU * DD) { ue = (const float*)d_in[i]; i_ue = i; }
        else if (s == (long long)NI * DD) { ie = (const float*)d_in[i]; i_ie = i; }
        else if (s == (long long)DD * NH) { if (!h1) h1 = (const float*)d_in[i]; else h2 = (const float*)d_in[i]; }
    }
    const float* uW; const float* iW;
    if (i_ue < i_ie) { uW = h1; iW = h2; }   // user-first convention (dict order)
    else             { uW = h2; iW = h1; }   // item-first (alphabetical)
    float* out = (float*)d_out;

    const int nb_nd  = (NN * DD / 4 + 255) / 256;        // 18750
    const int nb_hyp = (NN / 4 + 7) / 8;                 // 18750 blocks (8 warps x 4 rows) -- FIXED
    const int nb_spmm = (int)(((size_t)NE * 8 + 255) / 256); // 312500

    k_detect<<<1, 32>>>(adj);
    k_init<<<nb_nd, 256>>>(ue, ie, out);

    for (int layer = 0; layer < 2; layer++) {
        k_zeroG<<<1, 512>>>();
        k_G<<<GB_USER + GB_ITEM, 256>>>(ue, ie, layer);
        k_M<<<2, 256>>>(uW, iW);
        k_hyp<<<nb_hyp, 256>>>(ue, ie, layer);        // dst = hyp (init for spmm adds)
        k_spmm<<<nb_spmm, 256>>>(adj, vals, layer);
        k_accum<<<nb_nd, 256>>>(out, layer);
    }
}